// round 5
// baseline (speedup 1.0000x reference)
#include <cuda_runtime.h>

// CANN recurrent net, 14 iterations:
//   y_t = J @ s_{t-1};  U_t = y_t/recSum_{t-1} + Iext;  s_t = (0.2 U_t)^2;
//   recSum_t = K * sum(s_t)
// Outputs: U_14 (1680), recSum_14 (1), r_14 = s_14/recSum_14 (1680)
//
// Persistent grid (148 blocks, 1/SM), J rows register-resident (1 warp = 1 row).
// Per-row 64-bit token {tag|s-bits}, parity-buffered, monotonic tags (fence-free).
// Poll: sector-aligned v2.u64 loads, nanosleep backoff, value sums harvested
// during poll (recSum off the matvec path).

#define Nn     1680
#define NB     148
#define TPB    384
#define NWARP  12
#define ITERS  14
#define KC     0.005f
#define NTAIL  (Nn - 4 * TPB)   // 144 threads own a 5th slot

__device__ unsigned long long g_row[2][Nn];   // {tag:32 | s-bits:32}

__device__ __forceinline__ unsigned long long ldcg64(const unsigned long long* p) {
    unsigned long long v;
    asm volatile("ld.global.cg.u64 %0, [%1];" : "=l"(v) : "l"(p));
    return v;
}
__device__ __forceinline__ void ldcgv2(const unsigned long long* p,
                                       unsigned long long& a, unsigned long long& b) {
    asm volatile("ld.global.cg.v2.u64 {%0,%1}, [%2];" : "=l"(a), "=l"(b) : "l"(p));
}
__device__ __forceinline__ void stcg64(unsigned long long* p, unsigned long long v) {
    asm volatile("st.global.cg.u64 [%0], %1;" :: "l"(p), "l"(v) : "memory");
}

// Poll this thread's slots (4*tid .. 4*tid+3, plus 1536+tid if tid<144) for
// `target` tag; scatter values to s_sm; return fixed-order sum of the values.
__device__ __forceinline__ float poll_scatter(int par, unsigned target, int tid,
                                              float* s_sm) {
    unsigned long long* slots = g_row[par];
    const int r0 = 4 * tid;
    const unsigned need = (tid < NTAIL) ? 0x1fu : 0x0fu;
    float val[5] = {0.f, 0.f, 0.f, 0.f, 0.f};
    unsigned done = 0;
    int idle = 0;
    while (done != need) {
        unsigned long long v0 = 0, v1 = 0, v2 = 0, v3 = 0, v4 = 0;
        const unsigned pend = need & ~done;
        if (pend & 0x03u) ldcgv2(slots + r0, v0, v1);
        if (pend & 0x0cu) ldcgv2(slots + r0 + 2, v2, v3);
        if (pend & 0x10u) v4 = ldcg64(slots + 4 * TPB + tid);
        const unsigned before = done;
        if ((pend & 0x01u) && (unsigned)(v0 >> 32) == target) {
            val[0] = __uint_as_float((unsigned)v0); s_sm[r0 + 0] = val[0]; done |= 0x01u;
        }
        if ((pend & 0x02u) && (unsigned)(v1 >> 32) == target) {
            val[1] = __uint_as_float((unsigned)v1); s_sm[r0 + 1] = val[1]; done |= 0x02u;
        }
        if ((pend & 0x04u) && (unsigned)(v2 >> 32) == target) {
            val[2] = __uint_as_float((unsigned)v2); s_sm[r0 + 2] = val[2]; done |= 0x04u;
        }
        if ((pend & 0x08u) && (unsigned)(v3 >> 32) == target) {
            val[3] = __uint_as_float((unsigned)v3); s_sm[r0 + 3] = val[3]; done |= 0x08u;
        }
        if ((pend & 0x10u) && (unsigned)(v4 >> 32) == target) {
            val[4] = __uint_as_float((unsigned)v4); s_sm[4 * TPB + tid] = val[4]; done |= 0x10u;
        }
        if (done == before) { if (++idle >= 2) __nanosleep(64); }
        else idle = 0;
    }
    return ((val[0] + val[1]) + (val[2] + val[3])) + val[4];
}

__global__ void __launch_bounds__(TPB, 1)
cann_kernel(const float* __restrict__ net_in,
            const float* __restrict__ J,
            float* __restrict__ out)
{
    __shared__ __align__(16) float s_sm[Nn];   // staged s vector
    __shared__ float s_part[NWARP];            // per-warp token-value partials

    const int tid  = threadIdx.x;
    const int lane = tid & 31;
    const int wid  = tid >> 5;
    const int bid  = blockIdx.x;
    const int row  = wid * NB + bid;           // balanced 11-12 rows/block
    const bool active = (row < Nn);

    // Monotonic tag base: parity-0 slots all carry the same tag at run start
    // (t=14 is parity 0; parity-0 slots are first overwritten at t=2, which
    // requires every block to have already read its base).
    const unsigned base = (unsigned)(ldcg64(&g_row[0][4 * tid]) >> 32);

    const float iext = active ? __ldg(&net_in[row]) : 0.f;

    // ---- prologue: J row -> registers (1680 = 13*128 + 16 floats) ----
    float4 Jr[14];
    if (active) {
        const float4* Jp = reinterpret_cast<const float4*>(J + (size_t)row * Nn);
        #pragma unroll
        for (int j = 0; j < 13; ++j) Jr[j] = __ldg(&Jp[j * 32 + lane]);
        Jr[13] = (lane < 4) ? __ldg(&Jp[416 + lane]) : make_float4(0.f,0.f,0.f,0.f);
    }

    float lastS = 0.f, lastU = 0.f;

    for (int t = 1; t <= ITERS; ++t) {
        // ---- acquire s_{t-1} (poll doubles as grid barrier), harvest sum ----
        float rsT = 0.f;
        if (t == 1) {
            const float4* r4 = reinterpret_cast<const float4*>(net_in + Nn);
            for (int i = tid; i < Nn / 4; i += TPB)
                reinterpret_cast<float4*>(s_sm)[i] = __ldg(&r4[i]);
        } else {
            rsT = poll_scatter((t - 1) & 1, base + (unsigned)(t - 1), tid, s_sm);
        }
        // warp reduce token-value sums (fixed order -> deterministic)
        #pragma unroll
        for (int o = 16; o; o >>= 1) rsT += __shfl_xor_sync(0xffffffffu, rsT, o);
        if (lane == 0) s_part[wid] = rsT;
        __syncthreads();

        // block-wide sum(s_{t-1}): every warp reads the 12 partials (broadcast)
        float rsum = 0.f;
        #pragma unroll
        for (int w = 0; w < NWARP; ++w) rsum += s_part[w];
        const float invDen = (t == 1) ? 1.0f : 1.0f / (KC * rsum);

        // ---- matvec (register J row x smem s), publish immediately ----
        if (active) {
            const float4* s4 = reinterpret_cast<const float4*>(s_sm);
            float a0 = 0.f, a1 = 0.f;
            #pragma unroll
            for (int j = 0; j < 13; ++j) {
                float4 b = s4[j * 32 + lane];
                if (j & 1) {
                    a1 = fmaf(Jr[j].x, b.x, a1); a1 = fmaf(Jr[j].y, b.y, a1);
                    a1 = fmaf(Jr[j].z, b.z, a1); a1 = fmaf(Jr[j].w, b.w, a1);
                } else {
                    a0 = fmaf(Jr[j].x, b.x, a0); a0 = fmaf(Jr[j].y, b.y, a0);
                    a0 = fmaf(Jr[j].z, b.z, a0); a0 = fmaf(Jr[j].w, b.w, a0);
                }
            }
            if (lane < 4) {
                float4 b = s4[416 + lane];
                a1 = fmaf(Jr[13].x, b.x, a1); a1 = fmaf(Jr[13].y, b.y, a1);
                a1 = fmaf(Jr[13].z, b.z, a1); a1 = fmaf(Jr[13].w, b.w, a1);
            }
            float acc = a0 + a1;
            #pragma unroll
            for (int o = 16; o; o >>= 1) acc += __shfl_xor_sync(0xffffffffu, acc, o);
            if (lane == 0) {
                float U  = fmaf(acc, invDen, iext);
                float u2 = 0.2f * U;
                float sv = u2 * u2;
                stcg64(&g_row[t & 1][row],
                       ((unsigned long long)(base + (unsigned)t) << 32) |
                       (unsigned long long)__float_as_uint(sv));
                if (t == ITERS) { lastU = U; lastS = sv; }
            }
        }
        // No trailing barrier: tokens for t+1 can only appear after every block
        // (incl. this one) published t, so s_sm scatter for t+1 cannot race the
        // current matvec reads.
    }

    // ---- epilogue: stage s_14, recSum_14 = K*sum(s_14), write outputs ----
    {
        float rsT = poll_scatter(ITERS & 1, base + (unsigned)ITERS, tid, s_sm);
        #pragma unroll
        for (int o = 16; o; o >>= 1) rsT += __shfl_xor_sync(0xffffffffu, rsT, o);
        if (lane == 0) s_part[wid] = rsT;
    }
    __syncthreads();
    float rsum = 0.f;
    #pragma unroll
    for (int w = 0; w < NWARP; ++w) rsum += s_part[w];
    const float recS = KC * rsum;

    if (active && lane == 0) out[row] = lastU;           // U_14
    if (bid == 0) {
        if (tid == 0) out[Nn] = recS;                    // recSum_14
        for (int i = tid; i < Nn; i += TPB)              // r_14
            out[Nn + 1 + i] = s_sm[i] / recS;
    }
}

extern "C" void kernel_launch(void* const* d_in, const int* in_sizes, int n_in,
                              void* d_out, int out_size)
{
    const float* a = (const float*)d_in[0];
    const float* b = (const float*)d_in[1];
    const float* net_in = a;
    const float* J      = b;
    if (n_in >= 2 && in_sizes[0] > in_sizes[1]) { net_in = b; J = a; }
    cann_kernel<<<NB, TPB>>>(net_in, J, (float*)d_out);
}

// round 6
// speedup vs baseline: 2.2125x; 2.2125x over previous
#include <cuda_runtime.h>

// CANN recurrent net as a 15-node CUDA graph with Programmatic Dependent Launch.
//   step t: y = J @ s_{t-1};  U = y/recSum_{t-1} + Iext;  s_t = (0.2 U)^2
//   (recSum_{t-1} = K*sum(s_{t-1}) recomputed deterministically by every block)
//   finalize: recSum_14, r_14 = s_14/recSum_14
// Each step kernel prefetches its J rows into registers BEFORE griddepcontrol.wait
// (overlapping the predecessor via PDL + 2-CTA/SM co-residency), so the
// dependent critical path is only: stage 6.7KB s-vector + 56-FMA dot + store.

#define Nn     1680
#define NBLK   296
#define TPB    192          // 6 warps; 2 CTAs/SM
#define NWARP  6
#define ITERS  14
#define KC     0.005f

__device__ float g_s[2][Nn];   // unnormalized s vectors, parity-buffered

__device__ __forceinline__ void pdl_wait() {
    asm volatile("griddepcontrol.wait;" ::: "memory");
}
__device__ __forceinline__ void pdl_launch_dependents() {
    asm volatile("griddepcontrol.launch_dependents;" ::: "memory");
}
__device__ __forceinline__ float4 ldcg4(const float4* p) {
    float4 v;
    asm volatile("ld.global.cg.v4.f32 {%0,%1,%2,%3}, [%4];"
                 : "=f"(v.x), "=f"(v.y), "=f"(v.z), "=f"(v.w) : "l"(p));
    return v;
}

__global__ void __launch_bounds__(TPB, 2)
step_kernel(const float* __restrict__ net_in,
            const float* __restrict__ J,
            float* __restrict__ out,
            int t)
{
    __shared__ __align__(16) float s_sm[Nn];
    __shared__ float s_part[NWARP];

    const int tid  = threadIdx.x;
    const int lane = tid & 31;
    const int wid  = tid >> 5;
    const int bid  = blockIdx.x;
    const int row  = wid * NBLK + bid;       // 1680 = 5*296 + 200
    const bool active = (row < Nn);

    // ---- prefetch (independent of predecessor): J row -> regs, Iext ----
    float4 Jr[14];
    float iext = 0.f;
    if (active) {
        iext = __ldg(&net_in[row]);
        const float4* Jp = reinterpret_cast<const float4*>(J + (size_t)row * Nn);
        #pragma unroll
        for (int j = 0; j < 13; ++j) Jr[j] = __ldg(&Jp[j * 32 + lane]);
        Jr[13] = (lane < 4) ? __ldg(&Jp[416 + lane]) : make_float4(0.f,0.f,0.f,0.f);
    }

    pdl_launch_dependents();   // release next node's blocks for their prefetch
    pdl_wait();                // predecessor's g_s writes now visible

    // ---- stage s_{t-1} into smem + deterministic sum (identical everywhere) ----
    const float4* src = (t == 1)
        ? reinterpret_cast<const float4*>(net_in + Nn)
        : reinterpret_cast<const float4*>(g_s[(t - 1) & 1]);
    float rsT = 0.f;
    #pragma unroll
    for (int k = 0; k < 3; ++k) {
        int i = tid + k * TPB;
        if (i < Nn / 4) {
            float4 v = (t == 1) ? __ldg(&src[i]) : ldcg4(&src[i]);
            reinterpret_cast<float4*>(s_sm)[i] = v;
            rsT += (v.x + v.y) + (v.z + v.w);
        }
    }
    #pragma unroll
    for (int o = 16; o; o >>= 1) rsT += __shfl_xor_sync(0xffffffffu, rsT, o);
    if (lane == 0) s_part[wid] = rsT;
    __syncthreads();
    float rsum = 0.f;
    #pragma unroll
    for (int w = 0; w < NWARP; ++w) rsum += s_part[w];
    const float invDen = (t == 1) ? 1.0f : 1.0f / (KC * rsum);

    // ---- matvec (register J row x smem s), publish ----
    if (active) {
        const float4* s4 = reinterpret_cast<const float4*>(s_sm);
        float a0 = 0.f, a1 = 0.f;
        #pragma unroll
        for (int j = 0; j < 13; ++j) {
            float4 b = s4[j * 32 + lane];
            if (j & 1) {
                a1 = fmaf(Jr[j].x, b.x, a1); a1 = fmaf(Jr[j].y, b.y, a1);
                a1 = fmaf(Jr[j].z, b.z, a1); a1 = fmaf(Jr[j].w, b.w, a1);
            } else {
                a0 = fmaf(Jr[j].x, b.x, a0); a0 = fmaf(Jr[j].y, b.y, a0);
                a0 = fmaf(Jr[j].z, b.z, a0); a0 = fmaf(Jr[j].w, b.w, a0);
            }
        }
        if (lane < 4) {
            float4 b = s4[416 + lane];
            a1 = fmaf(Jr[13].x, b.x, a1); a1 = fmaf(Jr[13].y, b.y, a1);
            a1 = fmaf(Jr[13].z, b.z, a1); a1 = fmaf(Jr[13].w, b.w, a1);
        }
        float acc = a0 + a1;
        #pragma unroll
        for (int o = 16; o; o >>= 1) acc += __shfl_xor_sync(0xffffffffu, acc, o);
        if (lane == 0) {
            float U  = fmaf(acc, invDen, iext);
            float u2 = 0.2f * U;
            float sv = u2 * u2;
            g_s[t & 1][row] = sv;
            if (t == ITERS) out[row] = U;    // U_14
        }
    }
}

__global__ void __launch_bounds__(384)
final_kernel(float* __restrict__ out)
{
    __shared__ float s_part[12];
    const int tid = threadIdx.x, lane = tid & 31, wid = tid >> 5;

    pdl_wait();

    const float4* s4 = reinterpret_cast<const float4*>(g_s[ITERS & 1]);
    float v0s = 0.f, vals[2][4];
    bool has1 = (tid + 384) < Nn / 4;
    float4 a = ldcg4(&s4[tid]);
    vals[0][0]=a.x; vals[0][1]=a.y; vals[0][2]=a.z; vals[0][3]=a.w;
    float4 b = make_float4(0.f,0.f,0.f,0.f);
    if (has1) b = ldcg4(&s4[tid + 384]);
    vals[1][0]=b.x; vals[1][1]=b.y; vals[1][2]=b.z; vals[1][3]=b.w;
    v0s = ((a.x + a.y) + (a.z + a.w)) + ((b.x + b.y) + (b.z + b.w));
    #pragma unroll
    for (int o = 16; o; o >>= 1) v0s += __shfl_xor_sync(0xffffffffu, v0s, o);
    if (lane == 0) s_part[wid] = v0s;
    __syncthreads();
    float rsum = 0.f;
    #pragma unroll
    for (int w = 0; w < 12; ++w) rsum += s_part[w];
    const float recS = KC * rsum;

    if (tid == 0) out[Nn] = recS;                       // recSum_14
    #pragma unroll
    for (int e = 0; e < 4; ++e) {                       // r_14
        out[Nn + 1 + 4 * tid + e] = vals[0][e] / recS;
        if (has1) out[Nn + 1 + 4 * (tid + 384) + e] = vals[1][e] / recS;
    }
}

extern "C" void kernel_launch(void* const* d_in, const int* in_sizes, int n_in,
                              void* d_out, int out_size)
{
    const float* a = (const float*)d_in[0];
    const float* b = (const float*)d_in[1];
    const float* net_in = a;
    const float* J      = b;
    if (n_in >= 2 && in_sizes[0] > in_sizes[1]) { net_in = b; J = a; }
    float* out = (float*)d_out;

    cudaLaunchAttribute attr[1];
    attr[0].id = cudaLaunchAttributeProgrammaticStreamSerialization;
    attr[0].val.programmaticStreamSerializationAllowed = 1;

    cudaLaunchConfig_t cfg = {};
    cfg.gridDim  = dim3(NBLK, 1, 1);
    cfg.blockDim = dim3(TPB, 1, 1);
    cfg.dynamicSmemBytes = 0;
    cfg.stream = 0;            // legacy default stream (captured by harness)
    cfg.attrs = attr;
    cfg.numAttrs = 1;

    for (int t = 1; t <= ITERS; ++t)
        cudaLaunchKernelEx(&cfg, step_kernel, net_in, J, out, t);

    cudaLaunchConfig_t cfgF = cfg;
    cfgF.gridDim  = dim3(1, 1, 1);
    cfgF.blockDim = dim3(384, 1, 1);
    cudaLaunchKernelEx(&cfgF, final_kernel, out);
}